// round 1
// baseline (speedup 1.0000x reference)
#include <cuda_runtime.h>
#include <math.h>

#define NB 128
#define NH 512
#define NW 512
#define NP 64
#define ND 4

// ---------------- scratch (static device allocations, per harness rules) ----
__device__ float g_T1[(size_t)NB * NH * 512];   // x @ Wj      : [B][H][512]
__device__ float g_T2[(size_t)NB * NW * 512];   // x^T @ Wi    : [B][W][512]
__device__ float g_Wj[512 * 512];               // packed [o_xj(4) | o_rel_xj(4)]
__device__ float g_Wi[512 * 512];               // packed [o_xi(4) | o_rel_xi(4)]
__device__ float g_pt[(size_t)NB * ND * 2 * NP * NP]; // p_t_xj / p_t_xi
__device__ float g_relnum[NB * ND * 2 * NP];
__device__ float g_relden[NB * ND * 2];
__device__ float g_stats[NB * 2];               // mean*64, std*64

// ---------------- pack weights: Wj[w][g*64+p], g<4 -> proj, g>=4 -> rel -----
__global__ void __launch_bounds__(256) pack_kernel(
    const float* __restrict__ o_xj, const float* __restrict__ o_rel_xj,
    const float* __restrict__ o_xi, const float* __restrict__ o_rel_xi) {
    int idx = blockIdx.x * 256 + threadIdx.x;      // 0 .. 262143
    int w = idx >> 9;
    int n = idx & 511;
    int g = n >> 6, p = n & 63;
    float vj = (g < 4) ? o_xj[((size_t)g * 512 + w) * 64 + p]
                       : o_rel_xj[((size_t)(g - 4) * 512 + w) * 64 + p];
    float vi = (g < 4) ? o_xi[((size_t)g * 512 + w) * 64 + p]
                       : o_rel_xi[((size_t)(g - 4) * 512 + w) * 64 + p];
    g_Wj[idx] = vj;
    g_Wi[idx] = vi;
}

// ---------------- per-batch scaled mean/std of x ----------------------------
__global__ void __launch_bounds__(256) stats_kernel(const float* __restrict__ x) {
    int b = blockIdx.x;
    const float4* X4 = (const float4*)(x + (size_t)b * NH * NW);
    float s1 = 0.f, s2 = 0.f;
    for (int i = threadIdx.x; i < (NH * NW) / 4; i += 256) {
        float4 v = X4[i];
        s1 += v.x + v.y + v.z + v.w;
        s2 += v.x * v.x + v.y * v.y + v.z * v.z + v.w * v.w;
    }
    // block reduce
    for (int o = 16; o; o >>= 1) {
        s1 += __shfl_down_sync(0xffffffffu, s1, o);
        s2 += __shfl_down_sync(0xffffffffu, s2, o);
    }
    __shared__ float w1[8], w2[8];
    int t = threadIdx.x;
    if ((t & 31) == 0) { w1[t >> 5] = s1; w2[t >> 5] = s2; }
    __syncthreads();
    if (t == 0) {
        float S1 = 0.f, S2 = 0.f;
        for (int i = 0; i < 8; i++) { S1 += w1[i]; S2 += w2[i]; }
        const float n = (float)(NH * NW);
        float mean = S1 / n;
        float var = (S2 - S1 * S1 / n) / (n - 1.0f);
        g_stats[b * 2 + 0] = mean * 64.0f;           // scale = (H/P)*(W/P) = 64
        g_stats[b * 2 + 1] = sqrtf(var) * 64.0f;
    }
}

// ---------------- big GEMM: [512,512] x [512,512] per batch -----------------
// TRANSA=false: T1[b] = x[b]   @ Wj
// TRANSA=true : T2[b] = x[b]^T @ Wi
template <bool TRANSA>
__global__ void __launch_bounds__(256) gemm512_kernel(const float* __restrict__ x) {
    __shared__ float As[16][132];
    __shared__ float Bs[16][132];
    const int b = blockIdx.z;
    const int m0 = blockIdx.y * 128;
    const int n0 = blockIdx.x * 128;
    const float* A = x + (size_t)b * 512 * 512;
    const float* Wm = TRANSA ? g_Wi : g_Wj;
    float* O = (TRANSA ? g_T2 : g_T1) + (size_t)b * 512 * 512;

    const int tid = threadIdx.x;
    const int tx = tid & 15, ty = tid >> 4;

    float acc[8][8];
#pragma unroll
    for (int i = 0; i < 8; i++)
#pragma unroll
        for (int j = 0; j < 8; j++) acc[i][j] = 0.f;

    for (int k0 = 0; k0 < 512; k0 += 16) {
        if (TRANSA) {
#pragma unroll
            for (int l = 0; l < 2; ++l) {
                int pos = tid + l * 256;        // 0..511 over 16x32 float4s
                int r = pos >> 5, c4 = pos & 31;
                float4 v = *(const float4*)(A + (size_t)(k0 + r) * 512 + m0 + c4 * 4);
                *(float4*)(&As[r][c4 * 4]) = v;
            }
        } else {
#pragma unroll
            for (int l = 0; l < 2; ++l) {
                int pos = tid + l * 256;        // 128 rows x 4 float4s
                int r = pos >> 2, c4 = pos & 3;
                float4 v = *(const float4*)(A + (size_t)(m0 + r) * 512 + k0 + c4 * 4);
                As[c4 * 4 + 0][r] = v.x;
                As[c4 * 4 + 1][r] = v.y;
                As[c4 * 4 + 2][r] = v.z;
                As[c4 * 4 + 3][r] = v.w;
            }
        }
#pragma unroll
        for (int l = 0; l < 2; ++l) {
            int pos = tid + l * 256;
            int r = pos >> 5, c4 = pos & 31;
            float4 v = *(const float4*)(Wm + (size_t)(k0 + r) * 512 + n0 + c4 * 4);
            *(float4*)(&Bs[r][c4 * 4]) = v;
        }
        __syncthreads();
#pragma unroll
        for (int kk = 0; kk < 16; ++kk) {
            float a[8], bb[8];
            *(float4*)(a)     = *(const float4*)(&As[kk][ty * 4]);
            *(float4*)(a + 4) = *(const float4*)(&As[kk][64 + ty * 4]);
            *(float4*)(bb)     = *(const float4*)(&Bs[kk][tx * 4]);
            *(float4*)(bb + 4) = *(const float4*)(&Bs[kk][64 + tx * 4]);
#pragma unroll
            for (int i = 0; i < 8; i++)
#pragma unroll
                for (int j = 0; j < 8; j++) acc[i][j] += a[i] * bb[j];
        }
        __syncthreads();
    }
#pragma unroll
    for (int i = 0; i < 8; i++) {
        int m = m0 + ((i < 4) ? (ty * 4 + i) : (64 + ty * 4 + i - 4));
        *(float4*)(O + (size_t)m * 512 + n0 + tx * 4) =
            make_float4(acc[i][0], acc[i][1], acc[i][2], acc[i][3]);
        *(float4*)(O + (size_t)m * 512 + n0 + 64 + tx * 4) =
            make_float4(acc[i][4], acc[i][5], acc[i][6], acc[i][7]);
    }
}

// ---------------- big-branch softmax column sums ----------------------------
// For (b, d, side): columns (4+d)*64 .. +63 of T1 (side 0) / T2 (side 1).
// Produces relnum[p] = S_p * exp(M_p - Mg), relden = sum_p relnum[p].
__global__ void __launch_bounds__(256) rel_big_kernel() {
    int bx = blockIdx.x;                 // 0..7 : side*4 + d
    int side = bx >> 2, d = bx & 3;
    int b = blockIdx.y;
    const float* T = (side == 0 ? g_T1 : g_T2) + (size_t)b * 512 * 512 + (4 + d) * 64;
    int t = threadIdx.x;
    int p = t & 63, seg = t >> 6;

    float m = -1e30f, s = 0.f;
    const float* col = T + p;
    for (int h = seg * 128; h < seg * 128 + 128; ++h) {
        float v = col[(size_t)h * 512];
        if (v <= m) {
            s += __expf(v - m);
        } else {
            s = s * __expf(m - v) + 1.0f;
            m = v;
        }
    }
    __shared__ float sm[4][64], ss[4][64];
    __shared__ float sMp[64], sSp[64];
    __shared__ float sMg;
    sm[seg][p] = m;
    ss[seg][p] = s;
    __syncthreads();
    if (t < 64) {
        float M = sm[0][t];
        for (int g = 1; g < 4; g++) M = fmaxf(M, sm[g][t]);
        float S = 0.f;
        for (int g = 0; g < 4; g++) S += ss[g][t] * __expf(sm[g][t] - M);
        sMp[t] = M;
        sSp[t] = S;
    }
    __syncthreads();
    if (t == 0) {
        float mg = -1e30f;
        for (int q = 0; q < 64; q++) mg = fmaxf(mg, sMp[q]);
        sMg = mg;
    }
    __syncthreads();
    int base = (b * 4 + d) * 2 + side;
    if (t < 64) {
        float num = sSp[t] * __expf(sMp[t] - sMg);
        g_relnum[base * 64 + t] = num;
        sSp[t] = num;
    }
    __syncthreads();
    if (t == 0) {
        float tt = 0.f;
        for (int q = 0; q < 64; q++) tt += sSp[q];
        g_relden[base] = tt;
    }
}

// ---------------- p_t = T_proj^T @ p_w : [64,512] x [512,64] ---------------
__global__ void __launch_bounds__(256) pt_kernel(const float* __restrict__ p_xj,
                                                 const float* __restrict__ p_xi) {
    int bx = blockIdx.x;
    int side = bx >> 2, d = bx & 3;
    int b = blockIdx.y;
    const float* T = (side == 0 ? g_T1 : g_T2) + (size_t)b * 512 * 512 + d * 64;
    const float* Wp = (side == 0 ? p_xj : p_xi) + (size_t)d * 512 * 64;

    __shared__ float At[64][68];
    __shared__ float Bt[64][68];
    int tid = threadIdx.x;
    int tx = tid & 15, ty = tid >> 4;
    float acc[4][4];
#pragma unroll
    for (int i = 0; i < 4; i++)
#pragma unroll
        for (int j = 0; j < 4; j++) acc[i][j] = 0.f;

    for (int h0 = 0; h0 < 512; h0 += 64) {
#pragma unroll
        for (int l = 0; l < 4; ++l) {
            int pos = tid + l * 256;     // 64 rows x 16 float4s
            int r = pos >> 4, c4 = pos & 15;
            float4 va = *(const float4*)(T + (size_t)(h0 + r) * 512 + c4 * 4);
            *(float4*)(&At[r][c4 * 4]) = va;
            float4 vb = *(const float4*)(Wp + (size_t)(h0 + r) * 64 + c4 * 4);
            *(float4*)(&Bt[r][c4 * 4]) = vb;
        }
        __syncthreads();
#pragma unroll 8
        for (int hh = 0; hh < 64; ++hh) {
            float4 a = *(const float4*)(&At[hh][ty * 4]);
            float4 bb = *(const float4*)(&Bt[hh][tx * 4]);
            float av[4] = {a.x, a.y, a.z, a.w};
            float bv[4] = {bb.x, bb.y, bb.z, bb.w};
#pragma unroll
            for (int i = 0; i < 4; i++)
#pragma unroll
                for (int j = 0; j < 4; j++) acc[i][j] += av[i] * bv[j];
        }
        __syncthreads();
    }
    float* O = g_pt + (size_t)((b * 4 + d) * 2 + side) * 4096;
#pragma unroll
    for (int i = 0; i < 4; i++) {
        *(float4*)(O + (size_t)(ty * 4 + i) * 64 + tx * 4) =
            make_float4(acc[i][0], acc[i][1], acc[i][2], acc[i][3]);
    }
}

// ---------------- per-batch epilogue ---------------------------------------
// For each d: small softmax branches on p_t @ p_rel, f factors, x_buf
// assembly, renormalize, accumulate over depth, write out.
__global__ void __launch_bounds__(256) final_kernel(
    const float* __restrict__ p_rel_xj, const float* __restrict__ p_rel_xi,
    float* __restrict__ out) {
    int b = blockIdx.x;
    int t = threadIdx.x;
    __shared__ float bufA[4096];   // p_t tile
    __shared__ float bufB[4096];   // p_rel weights
    __shared__ float scr_m[256], scr_s[256], scr_f[64], sred[64];
    __shared__ float sVals[4];

    const int i_row = t >> 2;           // 0..63
    const int jbase = (t & 3) * 16;     // 0,16,32,48
    const float xmean = g_stats[b * 2 + 0];
    const float xstd  = g_stats[b * 2 + 1];

    float outacc[16];
#pragma unroll
    for (int jj = 0; jj < 16; jj++) outacc[jj] = 0.f;

    for (int d = 0; d < 4; ++d) {
        float xbuf[16];
#pragma unroll
        for (int jj = 0; jj < 16; jj++) xbuf[jj] = 0.f;

        for (int side = 0; side < 2; ++side) {
            __syncthreads();
            const float4* P4 = (const float4*)(g_pt + (size_t)((b * 4 + d) * 2 + side) * 4096);
            const float4* R4 = (const float4*)((side == 0 ? p_rel_xj : p_rel_xi) + (size_t)d * 4096);
#pragma unroll
            for (int l = 0; l < 4; l++) {
                ((float4*)bufA)[t + l * 256] = P4[t + l * 256];
                ((float4*)bufB)[t + l * 256] = R4[t + l * 256];
            }
            __syncthreads();

            // u = bufA @ bufB (64x64); column stats via 4 segs of 16 rows
            int c = t & 63, seg = t >> 6;
            float u[16];
#pragma unroll
            for (int r = 0; r < 16; r++) u[r] = 0.f;
            for (int k = 0; k < 64; ++k) {
                float bk = bufB[k * 64 + c];
#pragma unroll
                for (int r = 0; r < 16; r++)
                    u[r] += bufA[(seg * 16 + r) * 64 + k] * bk;
            }
            float m = u[0];
#pragma unroll
            for (int r = 1; r < 16; r++) m = fmaxf(m, u[r]);
            float s = 0.f;
#pragma unroll
            for (int r = 0; r < 16; r++) s += __expf(u[r] - m);
            scr_m[t] = m;
            scr_s[t] = s;
            __syncthreads();
            if (t < 64) {
                float M = scr_m[t];
                for (int g = 1; g < 4; g++) M = fmaxf(M, scr_m[g * 64 + t]);
                float S = 0.f;
                for (int g = 0; g < 4; g++) S += scr_s[g * 64 + t] * __expf(scr_m[g * 64 + t] - M);
                scr_m[t] = M;
                scr_s[t] = S;
            }
            __syncthreads();
            if (t == 0) {
                float mg = -1e30f;
                for (int q = 0; q < 64; q++) mg = fmaxf(mg, scr_m[q]);
                sVals[0] = mg;
            }
            __syncthreads();
            if (t < 64) {
                float num = scr_s[t] * __expf(scr_m[t] - sVals[0]);
                sred[t] = num;
                scr_s[t] = num;
            }
            __syncthreads();
            if (t == 0) {
                float tt = 0.f;
                for (int q = 0; q < 64; q++) tt += sred[q];
                sVals[1] = tt;
            }
            __syncthreads();
            int base = (b * 4 + d) * 2 + side;
            if (t < 64) {
                float onum = g_relnum[base * 64 + t];
                float oden = g_relden[base];
                // f = sqrt( (onum/oden) / (num/T) )
                scr_f[t] = sqrtf(onum * sVals[1] / (oden * scr_s[t]));
            }
            __syncthreads();
            if (side == 0) {
                float fi = scr_f[i_row];
#pragma unroll
                for (int jj = 0; jj < 16; jj++)
                    xbuf[jj] += bufA[i_row * 64 + jbase + jj] * fi;
            } else {
#pragma unroll
                for (int jj = 0; jj < 16; jj++) {
                    int j = jbase + jj;
                    xbuf[jj] += bufA[j * 64 + i_row] * scr_f[j];
                }
            }
        }
        // mean/std (ddof=1) over 4096 values of xbuf
        float s1 = 0.f, s2 = 0.f;
#pragma unroll
        for (int jj = 0; jj < 16; jj++) {
            s1 += xbuf[jj];
            s2 += xbuf[jj] * xbuf[jj];
        }
        for (int o = 16; o; o >>= 1) {
            s1 += __shfl_down_sync(0xffffffffu, s1, o);
            s2 += __shfl_down_sync(0xffffffffu, s2, o);
        }
        __syncthreads();           // protect scr_m reuse
        if ((t & 31) == 0) {
            scr_m[t >> 5] = s1;
            scr_s[t >> 5] = s2;
        }
        __syncthreads();
        if (t == 0) {
            float S1 = 0.f, S2 = 0.f;
            for (int wv = 0; wv < 8; wv++) { S1 += scr_m[wv]; S2 += scr_s[wv]; }
            float mean = S1 * (1.0f / 4096.0f);
            float var = (S2 - 4096.0f * mean * mean) * (1.0f / 4095.0f);
            sVals[2] = mean;
            sVals[3] = xstd / (sqrtf(var) + 1e-5f);
        }
        __syncthreads();
#pragma unroll
        for (int jj = 0; jj < 16; jj++)
            outacc[jj] += (xbuf[jj] - sVals[2]) * sVals[3] + xmean;
    }
    float* O = out + (size_t)b * 4096;
#pragma unroll
    for (int jj = 0; jj < 16; jj++)
        O[(size_t)i_row * 64 + jbase + jj] = outacc[jj];
}

// ---------------- launch -----------------------------------------------------
extern "C" void kernel_launch(void* const* d_in, const int* in_sizes, int n_in,
                              void* d_out, int out_size) {
    const float* x        = (const float*)d_in[0];
    const float* o_xj     = (const float*)d_in[1];
    const float* o_xi     = (const float*)d_in[2];
    const float* p_xj     = (const float*)d_in[3];
    const float* p_xi     = (const float*)d_in[4];
    const float* o_rel_xj = (const float*)d_in[5];
    const float* o_rel_xi = (const float*)d_in[6];
    const float* p_rel_xj = (const float*)d_in[7];
    const float* p_rel_xi = (const float*)d_in[8];
    float* out = (float*)d_out;

    pack_kernel<<<1024, 256>>>(o_xj, o_rel_xj, o_xi, o_rel_xi);
    stats_kernel<<<NB, 256>>>(x);
    gemm512_kernel<false><<<dim3(4, 4, NB), 256>>>(x);
    gemm512_kernel<true><<<dim3(4, 4, NB), 256>>>(x);
    rel_big_kernel<<<dim3(8, NB), 256>>>();
    pt_kernel<<<dim3(8, NB), 256>>>(p_xj, p_xi);
    final_kernel<<<NB, 256>>>(p_rel_xj, p_rel_xi, out);
}

// round 2
// speedup vs baseline: 1.0025x; 1.0025x over previous
#include <cuda_runtime.h>
#include <math.h>

#define NB 128
#define NH 512
#define NW 512
#define NP 64
#define ND 4

// ---------------- scratch (static device allocations, per harness rules) ----
__device__ float g_T1[(size_t)NB * NH * 512];   // x @ Wj      : [B][H][512]
__device__ float g_T2[(size_t)NB * NW * 512];   // x^T @ Wi    : [B][W][512]
__device__ float g_Wj[512 * 512];               // packed [o_xj(4) | o_rel_xj(4)]
__device__ float g_Wi[512 * 512];               // packed [o_xi(4) | o_rel_xi(4)]
__device__ float g_pt[(size_t)NB * ND * 2 * NP * NP]; // p_t_xj / p_t_xi
__device__ float g_relnum[NB * ND * 2 * NP];
__device__ float g_relden[NB * ND * 2];
__device__ float g_stats[NB * 2];               // mean*64, std*64

// ---------------- pack weights: Wj[w][g*64+p], g<4 -> proj, g>=4 -> rel -----
__global__ void __launch_bounds__(256) pack_kernel(
    const float* __restrict__ o_xj, const float* __restrict__ o_rel_xj,
    const float* __restrict__ o_xi, const float* __restrict__ o_rel_xi) {
    int idx = blockIdx.x * 256 + threadIdx.x;      // 0 .. 262143
    int w = idx >> 9;
    int n = idx & 511;
    int g = n >> 6, p = n & 63;
    float vj = (g < 4) ? o_xj[((size_t)g * 512 + w) * 64 + p]
                       : o_rel_xj[((size_t)(g - 4) * 512 + w) * 64 + p];
    float vi = (g < 4) ? o_xi[((size_t)g * 512 + w) * 64 + p]
                       : o_rel_xi[((size_t)(g - 4) * 512 + w) * 64 + p];
    g_Wj[idx] = vj;
    g_Wi[idx] = vi;
}

// ---------------- per-batch scaled mean/std of x ----------------------------
__global__ void __launch_bounds__(256) stats_kernel(const float* __restrict__ x) {
    int b = blockIdx.x;
    const float4* X4 = (const float4*)(x + (size_t)b * NH * NW);
    float s1 = 0.f, s2 = 0.f;
    for (int i = threadIdx.x; i < (NH * NW) / 4; i += 256) {
        float4 v = X4[i];
        s1 += v.x + v.y + v.z + v.w;
        s2 += v.x * v.x + v.y * v.y + v.z * v.z + v.w * v.w;
    }
    // block reduce
    for (int o = 16; o; o >>= 1) {
        s1 += __shfl_down_sync(0xffffffffu, s1, o);
        s2 += __shfl_down_sync(0xffffffffu, s2, o);
    }
    __shared__ float w1[8], w2[8];
    int t = threadIdx.x;
    if ((t & 31) == 0) { w1[t >> 5] = s1; w2[t >> 5] = s2; }
    __syncthreads();
    if (t == 0) {
        float S1 = 0.f, S2 = 0.f;
        for (int i = 0; i < 8; i++) { S1 += w1[i]; S2 += w2[i]; }
        const float n = (float)(NH * NW);
        float mean = S1 / n;
        float var = (S2 - S1 * S1 / n) / (n - 1.0f);
        g_stats[b * 2 + 0] = mean * 64.0f;           // scale = (H/P)*(W/P) = 64
        g_stats[b * 2 + 1] = sqrtf(var) * 64.0f;
    }
}

// ---------------- big GEMM: [512,512] x [512,512] per batch -----------------
// TRANSA=false: T1[b] = x[b]   @ Wj
// TRANSA=true : T2[b] = x[b]^T @ Wi
template <bool TRANSA>
__global__ void __launch_bounds__(256) gemm512_kernel(const float* __restrict__ x) {
    __shared__ float As[16][132];
    __shared__ float Bs[16][132];
    const int b = blockIdx.z;
    const int m0 = blockIdx.y * 128;
    const int n0 = blockIdx.x * 128;
    const float* A = x + (size_t)b * 512 * 512;
    const float* Wm = TRANSA ? g_Wi : g_Wj;
    float* O = (TRANSA ? g_T2 : g_T1) + (size_t)b * 512 * 512;

    const int tid = threadIdx.x;
    const int tx = tid & 15, ty = tid >> 4;

    float acc[8][8];
#pragma unroll
    for (int i = 0; i < 8; i++)
#pragma unroll
        for (int j = 0; j < 8; j++) acc[i][j] = 0.f;

    for (int k0 = 0; k0 < 512; k0 += 16) {
        if (TRANSA) {
#pragma unroll
            for (int l = 0; l < 2; ++l) {
                int pos = tid + l * 256;        // 0..511 over 16x32 float4s
                int r = pos >> 5, c4 = pos & 31;
                float4 v = *(const float4*)(A + (size_t)(k0 + r) * 512 + m0 + c4 * 4);
                *(float4*)(&As[r][c4 * 4]) = v;
            }
        } else {
#pragma unroll
            for (int l = 0; l < 2; ++l) {
                int pos = tid + l * 256;        // 128 rows x 4 float4s
                int r = pos >> 2, c4 = pos & 3;
                float4 v = *(const float4*)(A + (size_t)(m0 + r) * 512 + k0 + c4 * 4);
                As[c4 * 4 + 0][r] = v.x;
                As[c4 * 4 + 1][r] = v.y;
                As[c4 * 4 + 2][r] = v.z;
                As[c4 * 4 + 3][r] = v.w;
            }
        }
#pragma unroll
        for (int l = 0; l < 2; ++l) {
            int pos = tid + l * 256;
            int r = pos >> 5, c4 = pos & 31;
            float4 v = *(const float4*)(Wm + (size_t)(k0 + r) * 512 + n0 + c4 * 4);
            *(float4*)(&Bs[r][c4 * 4]) = v;
        }
        __syncthreads();
#pragma unroll
        for (int kk = 0; kk < 16; ++kk) {
            float a[8], bb[8];
            *(float4*)(a)     = *(const float4*)(&As[kk][ty * 4]);
            *(float4*)(a + 4) = *(const float4*)(&As[kk][64 + ty * 4]);
            *(float4*)(bb)     = *(const float4*)(&Bs[kk][tx * 4]);
            *(float4*)(bb + 4) = *(const float4*)(&Bs[kk][64 + tx * 4]);
#pragma unroll
            for (int i = 0; i < 8; i++)
#pragma unroll
                for (int j = 0; j < 8; j++) acc[i][j] += a[i] * bb[j];
        }
        __syncthreads();
    }
#pragma unroll
    for (int i = 0; i < 8; i++) {
        int m = m0 + ((i < 4) ? (ty * 4 + i) : (64 + ty * 4 + i - 4));
        *(float4*)(O + (size_t)m * 512 + n0 + tx * 4) =
            make_float4(acc[i][0], acc[i][1], acc[i][2], acc[i][3]);
        *(float4*)(O + (size_t)m * 512 + n0 + 64 + tx * 4) =
            make_float4(acc[i][4], acc[i][5], acc[i][6], acc[i][7]);
    }
}

// ---------------- big-branch softmax column sums ----------------------------
// For (b, d, side): columns (4+d)*64 .. +63 of T1 (side 0) / T2 (side 1).
// Produces relnum[p] = S_p * exp(M_p - Mg), relden = sum_p relnum[p].
__global__ void __launch_bounds__(256) rel_big_kernel() {
    int bx = blockIdx.x;                 // 0..7 : side*4 + d
    int side = bx >> 2, d = bx & 3;
    int b = blockIdx.y;
    const float* T = (side == 0 ? g_T1 : g_T2) + (size_t)b * 512 * 512 + (4 + d) * 64;
    int t = threadIdx.x;
    int p = t & 63, seg = t >> 6;

    float m = -1e30f, s = 0.f;
    const float* col = T + p;
    for (int h = seg * 128; h < seg * 128 + 128; ++h) {
        float v = col[(size_t)h * 512];
        if (v <= m) {
            s += __expf(v - m);
        } else {
            s = s * __expf(m - v) + 1.0f;
            m = v;
        }
    }
    __shared__ float sm[4][64], ss[4][64];
    __shared__ float sMp[64], sSp[64];
    __shared__ float sMg;
    sm[seg][p] = m;
    ss[seg][p] = s;
    __syncthreads();
    if (t < 64) {
        float M = sm[0][t];
        for (int g = 1; g < 4; g++) M = fmaxf(M, sm[g][t]);
        float S = 0.f;
        for (int g = 0; g < 4; g++) S += ss[g][t] * __expf(sm[g][t] - M);
        sMp[t] = M;
        sSp[t] = S;
    }
    __syncthreads();
    if (t == 0) {
        float mg = -1e30f;
        for (int q = 0; q < 64; q++) mg = fmaxf(mg, sMp[q]);
        sMg = mg;
    }
    __syncthreads();
    int base = (b * 4 + d) * 2 + side;
    if (t < 64) {
        float num = sSp[t] * __expf(sMp[t] - sMg);
        g_relnum[base * 64 + t] = num;
        sSp[t] = num;
    }
    __syncthreads();
    if (t == 0) {
        float tt = 0.f;
        for (int q = 0; q < 64; q++) tt += sSp[q];
        g_relden[base] = tt;
    }
}

// ---------------- p_t = T_proj^T @ p_w : [64,512] x [512,64] ---------------
__global__ void __launch_bounds__(256) pt_kernel(const float* __restrict__ p_xj,
                                                 const float* __restrict__ p_xi) {
    int bx = blockIdx.x;
    int side = bx >> 2, d = bx & 3;
    int b = blockIdx.y;
    const float* T = (side == 0 ? g_T1 : g_T2) + (size_t)b * 512 * 512 + d * 64;
    const float* Wp = (side == 0 ? p_xj : p_xi) + (size_t)d * 512 * 64;

    __shared__ float At[64][68];
    __shared__ float Bt[64][68];
    int tid = threadIdx.x;
    int tx = tid & 15, ty = tid >> 4;
    float acc[4][4];
#pragma unroll
    for (int i = 0; i < 4; i++)
#pragma unroll
        for (int j = 0; j < 4; j++) acc[i][j] = 0.f;

    for (int h0 = 0; h0 < 512; h0 += 64) {
#pragma unroll
        for (int l = 0; l < 4; ++l) {
            int pos = tid + l * 256;     // 64 rows x 16 float4s
            int r = pos >> 4, c4 = pos & 15;
            float4 va = *(const float4*)(T + (size_t)(h0 + r) * 512 + c4 * 4);
            *(float4*)(&At[r][c4 * 4]) = va;
            float4 vb = *(const float4*)(Wp + (size_t)(h0 + r) * 64 + c4 * 4);
            *(float4*)(&Bt[r][c4 * 4]) = vb;
        }
        __syncthreads();
#pragma unroll 8
        for (int hh = 0; hh < 64; ++hh) {
            float4 a = *(const float4*)(&At[hh][ty * 4]);
            float4 bb = *(const float4*)(&Bt[hh][tx * 4]);
            float av[4] = {a.x, a.y, a.z, a.w};
            float bv[4] = {bb.x, bb.y, bb.z, bb.w};
#pragma unroll
            for (int i = 0; i < 4; i++)
#pragma unroll
                for (int j = 0; j < 4; j++) acc[i][j] += av[i] * bv[j];
        }
        __syncthreads();
    }
    float* O = g_pt + (size_t)((b * 4 + d) * 2 + side) * 4096;
#pragma unroll
    for (int i = 0; i < 4; i++) {
        *(float4*)(O + (size_t)(ty * 4 + i) * 64 + tx * 4) =
            make_float4(acc[i][0], acc[i][1], acc[i][2], acc[i][3]);
    }
}

// ---------------- per-batch epilogue ---------------------------------------
// For each d: small softmax branches on p_t @ p_rel, f factors, x_buf
// assembly, renormalize, accumulate over depth, write out.
__global__ void __launch_bounds__(256) final_kernel(
    const float* __restrict__ p_rel_xj, const float* __restrict__ p_rel_xi,
    float* __restrict__ out) {
    int b = blockIdx.x;
    int t = threadIdx.x;
    __shared__ float bufA[4096];   // p_t tile
    __shared__ float bufB[4096];   // p_rel weights
    __shared__ float scr_m[256], scr_s[256], scr_f[64], sred[64];
    __shared__ float sVals[4];

    const int i_row = t >> 2;           // 0..63
    const int jbase = (t & 3) * 16;     // 0,16,32,48
    const float xmean = g_stats[b * 2 + 0];
    const float xstd  = g_stats[b * 2 + 1];

    float outacc[16];
#pragma unroll
    for (int jj = 0; jj < 16; jj++) outacc[jj] = 0.f;

    for (int d = 0; d < 4; ++d) {
        float xbuf[16];
#pragma unroll
        for (int jj = 0; jj < 16; jj++) xbuf[jj] = 0.f;

        for (int side = 0; side < 2; ++side) {
            __syncthreads();
            const float4* P4 = (const float4*)(g_pt + (size_t)((b * 4 + d) * 2 + side) * 4096);
            const float4* R4 = (const float4*)((side == 0 ? p_rel_xj : p_rel_xi) + (size_t)d * 4096);
#pragma unroll
            for (int l = 0; l < 4; l++) {
                ((float4*)bufA)[t + l * 256] = P4[t + l * 256];
                ((float4*)bufB)[t + l * 256] = R4[t + l * 256];
            }
            __syncthreads();

            // u = bufA @ bufB (64x64); column stats via 4 segs of 16 rows
            int c = t & 63, seg = t >> 6;
            float u[16];
#pragma unroll
            for (int r = 0; r < 16; r++) u[r] = 0.f;
            for (int k = 0; k < 64; ++k) {
                float bk = bufB[k * 64 + c];
#pragma unroll
                for (int r = 0; r < 16; r++)
                    u[r] += bufA[(seg * 16 + r) * 64 + k] * bk;
            }
            float m = u[0];
#pragma unroll
            for (int r = 1; r < 16; r++) m = fmaxf(m, u[r]);
            float s = 0.f;
#pragma unroll
            for (int r = 0; r < 16; r++) s += __expf(u[r] - m);
            scr_m[t] = m;
            scr_s[t] = s;
            __syncthreads();
            if (t < 64) {
                float M = scr_m[t];
                for (int g = 1; g < 4; g++) M = fmaxf(M, scr_m[g * 64 + t]);
                float S = 0.f;
                for (int g = 0; g < 4; g++) S += scr_s[g * 64 + t] * __expf(scr_m[g * 64 + t] - M);
                scr_m[t] = M;
                scr_s[t] = S;
            }
            __syncthreads();
            if (t == 0) {
                float mg = -1e30f;
                for (int q = 0; q < 64; q++) mg = fmaxf(mg, scr_m[q]);
                sVals[0] = mg;
            }
            __syncthreads();
            if (t < 64) {
                float num = scr_s[t] * __expf(scr_m[t] - sVals[0]);
                sred[t] = num;
                scr_s[t] = num;
            }
            __syncthreads();
            if (t == 0) {
                float tt = 0.f;
                for (int q = 0; q < 64; q++) tt += sred[q];
                sVals[1] = tt;
            }
            __syncthreads();
            int base = (b * 4 + d) * 2 + side;
            if (t < 64) {
                float onum = g_relnum[base * 64 + t];
                float oden = g_relden[base];
                // f = sqrt( (onum/oden) / (num/T) )
                scr_f[t] = sqrtf(onum * sVals[1] / (oden * scr_s[t]));
            }
            __syncthreads();
            if (side == 0) {
                float fi = scr_f[i_row];
#pragma unroll
                for (int jj = 0; jj < 16; jj++)
                    xbuf[jj] += bufA[i_row * 64 + jbase + jj] * fi;
            } else {
#pragma unroll
                for (int jj = 0; jj < 16; jj++) {
                    int j = jbase + jj;
                    xbuf[jj] += bufA[j * 64 + i_row] * scr_f[j];
                }
            }
        }
        // mean/std (ddof=1) over 4096 values of xbuf
        float s1 = 0.f, s2 = 0.f;
#pragma unroll
        for (int jj = 0; jj < 16; jj++) {
            s1 += xbuf[jj];
            s2 += xbuf[jj] * xbuf[jj];
        }
        for (int o = 16; o; o >>= 1) {
            s1 += __shfl_down_sync(0xffffffffu, s1, o);
            s2 += __shfl_down_sync(0xffffffffu, s2, o);
        }
        __syncthreads();           // protect scr_m reuse
        if ((t & 31) == 0) {
            scr_m[t >> 5] = s1;
            scr_s[t >> 5] = s2;
        }
        __syncthreads();
        if (t == 0) {
            float S1 = 0.f, S2 = 0.f;
            for (int wv = 0; wv < 8; wv++) { S1 += scr_m[wv]; S2 += scr_s[wv]; }
            float mean = S1 * (1.0f / 4096.0f);
            float var = (S2 - 4096.0f * mean * mean) * (1.0f / 4095.0f);
            sVals[2] = mean;
            sVals[3] = xstd / (sqrtf(var) + 1e-5f);
        }
        __syncthreads();
#pragma unroll
        for (int jj = 0; jj < 16; jj++)
            outacc[jj] += (xbuf[jj] - sVals[2]) * sVals[3] + xmean;
    }
    float* O = out + (size_t)b * 4096;
#pragma unroll
    for (int jj = 0; jj < 16; jj++)
        O[(size_t)i_row * 64 + jbase + jj] = outacc[jj];
}

// ---------------- launch -----------------------------------------------------
extern "C" void kernel_launch(void* const* d_in, const int* in_sizes, int n_in,
                              void* d_out, int out_size) {
    const float* x        = (const float*)d_in[0];
    const float* o_xj     = (const float*)d_in[1];
    const float* o_xi     = (const float*)d_in[2];
    const float* p_xj     = (const float*)d_in[3];
    const float* p_xi     = (const float*)d_in[4];
    const float* o_rel_xj = (const float*)d_in[5];
    const float* o_rel_xi = (const float*)d_in[6];
    const float* p_rel_xj = (const float*)d_in[7];
    const float* p_rel_xi = (const float*)d_in[8];
    float* out = (float*)d_out;

    pack_kernel<<<1024, 256>>>(o_xj, o_rel_xj, o_xi, o_rel_xi);
    stats_kernel<<<NB, 256>>>(x);
    gemm512_kernel<false><<<dim3(4, 4, NB), 256>>>(x);
    gemm512_kernel<true><<<dim3(4, 4, NB), 256>>>(x);
    rel_big_kernel<<<dim3(8, NB), 256>>>();
    pt_kernel<<<dim3(8, NB), 256>>>(p_xj, p_xi);
    final_kernel<<<NB, 256>>>(p_rel_xj, p_rel_xi, out);
}

// round 7
// speedup vs baseline: 2.1109x; 2.1056x over previous
#include <cuda_runtime.h>
#include <math.h>
#include <stdint.h>

#define NB 128
#define NP 64
#define ND 4

// ---------------- scratch ----------------------------------------------------
__device__ float g_T1[(size_t)NB * 512 * 512];   // x @ Wj
__device__ float g_T2[(size_t)NB * 512 * 512];   // x^T @ Wi
__device__ float g_Wjt[512 * 512];               // [n][k] transposed packed weights
__device__ float g_Wit[512 * 512];
__device__ float g_pt[(size_t)NB * ND * 2 * NP * NP];
__device__ float g_relnum[NB * ND * 2 * NP];
__device__ float g_relden[NB * ND * 2];
__device__ float g_stats[NB * 2];

// ---------------- helpers ----------------------------------------------------
__device__ __forceinline__ uint32_t smem_u32(const void* p) {
    uint32_t a;
    asm("{ .reg .u64 t; cvta.to.shared.u64 t, %1; cvt.u32.u64 %0, t; }" : "=r"(a) : "l"(p));
    return a;
}
__device__ __forceinline__ void cp16(uint32_t d, const void* s) {
    asm volatile("cp.async.cg.shared.global [%0], [%1], 16;" :: "r"(d), "l"(s));
}
#define CP_COMMIT() asm volatile("cp.async.commit_group;" ::: "memory")
#define CP_WAIT(n) asm volatile("cp.async.wait_group %0;" :: "n"(n) : "memory")

__device__ __forceinline__ uint32_t f2tf(float f) {
    uint32_t r;
    asm("cvt.rna.tf32.f32 %0, %1;" : "=r"(r) : "f"(f));
    return r;
}
__device__ __forceinline__ void mma_tf32(float* d, const uint32_t* a, const uint32_t* b) {
    asm volatile(
        "mma.sync.aligned.m16n8k8.row.col.f32.tf32.tf32.f32 "
        "{%0,%1,%2,%3}, {%4,%5,%6,%7}, {%8,%9}, {%0,%1,%2,%3};"
        : "+f"(d[0]), "+f"(d[1]), "+f"(d[2]), "+f"(d[3])
        : "r"(a[0]), "r"(a[1]), "r"(a[2]), "r"(a[3]), "r"(b[0]), "r"(b[1]));
}

// ---------------- pack weights transposed: Wt[n][k] --------------------------
__global__ void __launch_bounds__(256) pack_kernel(
    const float* __restrict__ o_xj, const float* __restrict__ o_rel_xj,
    const float* __restrict__ o_xi, const float* __restrict__ o_rel_xi) {
    int idx = blockIdx.x * 256 + threadIdx.x;      // 0..262143
    int n = idx >> 9, k = idx & 511;
    int g = n >> 6, p = n & 63;
    g_Wjt[idx] = (g < 4) ? o_xj[((size_t)g * 512 + k) * 64 + p]
                         : o_rel_xj[((size_t)(g - 4) * 512 + k) * 64 + p];
    g_Wit[idx] = (g < 4) ? o_xi[((size_t)g * 512 + k) * 64 + p]
                         : o_rel_xi[((size_t)(g - 4) * 512 + k) * 64 + p];
}

// ---------------- per-batch scaled mean/std ---------------------------------
__global__ void __launch_bounds__(256) stats_kernel(const float* __restrict__ x) {
    int b = blockIdx.x;
    const float4* X4 = (const float4*)(x + (size_t)b * 512 * 512);
    float s1 = 0.f, s2 = 0.f;
    for (int i = threadIdx.x; i < (512 * 512) / 4; i += 256) {
        float4 v = X4[i];
        s1 += v.x + v.y + v.z + v.w;
        s2 += v.x * v.x + v.y * v.y + v.z * v.z + v.w * v.w;
    }
    for (int o = 16; o; o >>= 1) {
        s1 += __shfl_down_sync(0xffffffffu, s1, o);
        s2 += __shfl_down_sync(0xffffffffu, s2, o);
    }
    __shared__ float w1[8], w2[8];
    int t = threadIdx.x;
    if ((t & 31) == 0) { w1[t >> 5] = s1; w2[t >> 5] = s2; }
    __syncthreads();
    if (t == 0) {
        float S1 = 0.f, S2 = 0.f;
        for (int i = 0; i < 8; i++) { S1 += w1[i]; S2 += w2[i]; }
        const float n = 262144.0f;
        float mean = S1 / n;
        float var = (S2 - S1 * S1 / n) / (n - 1.0f);
        g_stats[b * 2 + 0] = mean * 64.0f;
        g_stats[b * 2 + 1] = sqrtf(var) * 64.0f;
    }
}

// ---------------- tf32 tensor-core GEMM (static smem, <=48KB) ----------------
// WHICH=0: T1[b] = x[b] @ Wjt^T      (A[m][k] = x[m][k], stage As[128][20])
// WHICH=1: T2[b] = x[b]^T @ Wit^T    (A[m][k] = x[k][m], stage As[16][136])
// CTA tile 128x128, KC=16, double-buffered cp.async, 8 warps (2x4), warp 64x32.
template <int WHICH>
__global__ void __launch_bounds__(256) gemm_tf32_kernel(const float* __restrict__ x) {
    __shared__ float sA[2][2560];
    __shared__ float sB[2][2560];
    const int b = blockIdx.z, n0 = blockIdx.x * 128, m0 = blockIdx.y * 128;
    const float* A = x + (size_t)b * 512 * 512;
    const float* W = WHICH ? g_Wit : g_Wjt;
    float* Out = (WHICH ? g_T2 : g_T1) + (size_t)b * 512 * 512;
    const int tid = threadIdx.x, wid = tid >> 5, lane = tid & 31;
    const int m0w = (wid >> 2) * 64, n0w = (wid & 3) * 32;
    const int lr = lane >> 2, lc = lane & 3;

    float acc[4][4][4];
#pragma unroll
    for (int i = 0; i < 4; i++)
#pragma unroll
        for (int j = 0; j < 4; j++)
#pragma unroll
            for (int r = 0; r < 4; r++) acc[i][j][r] = 0.f;

    auto load_stage = [&](int st, int k0) {
        uint32_t ab = smem_u32(&sA[st][0]);
        if (WHICH == 0) {
#pragma unroll
            for (int i = 0; i < 2; i++) {
                int idx = tid + i * 256, r = idx >> 2, sg = idx & 3;
                cp16(ab + r * 80 + sg * 16, A + (size_t)(m0 + r) * 512 + k0 + sg * 4);
            }
        } else {
#pragma unroll
            for (int i = 0; i < 2; i++) {
                int idx = tid + i * 256, r = idx >> 5, sg = idx & 31;
                cp16(ab + r * 544 + sg * 16, A + (size_t)(k0 + r) * 512 + m0 + sg * 4);
            }
        }
        uint32_t bb = smem_u32(&sB[st][0]);
#pragma unroll
        for (int i = 0; i < 2; i++) {
            int idx = tid + i * 256, r = idx >> 2, sg = idx & 3;
            cp16(bb + r * 80 + sg * 16, W + (size_t)(n0 + r) * 512 + k0 + sg * 4);
        }
    };

    load_stage(0, 0);
    CP_COMMIT();
    load_stage(1, 16);
    CP_COMMIT();

    for (int c = 0; c < 32; ++c) {
        if (c < 31) { CP_WAIT(1); } else { CP_WAIT(0); }
        __syncthreads();
        const float* As = sA[c & 1];
        const float* Bs = sB[c & 1];
#pragma unroll
        for (int s = 0; s < 2; ++s) {
            const int k0c = s * 8;
            uint32_t af[4][4], bf[4][2];
#pragma unroll
            for (int mt = 0; mt < 4; ++mt) {
                int row = m0w + mt * 16 + lr;
                if (WHICH == 0) {
                    af[mt][0] = f2tf(As[row * 20 + k0c + lc]);
                    af[mt][1] = f2tf(As[(row + 8) * 20 + k0c + lc]);
                    af[mt][2] = f2tf(As[row * 20 + k0c + lc + 4]);
                    af[mt][3] = f2tf(As[(row + 8) * 20 + k0c + lc + 4]);
                } else {
                    af[mt][0] = f2tf(As[(k0c + lc) * 136 + row]);
                    af[mt][1] = f2tf(As[(k0c + lc) * 136 + row + 8]);
                    af[mt][2] = f2tf(As[(k0c + lc + 4) * 136 + row]);
                    af[mt][3] = f2tf(As[(k0c + lc + 4) * 136 + row + 8]);
                }
            }
#pragma unroll
            for (int nt = 0; nt < 4; ++nt) {
                int nrow = n0w + nt * 8 + lr;
                bf[nt][0] = f2tf(Bs[nrow * 20 + k0c + lc]);
                bf[nt][1] = f2tf(Bs[nrow * 20 + k0c + lc + 4]);
            }
#pragma unroll
            for (int mt = 0; mt < 4; ++mt)
#pragma unroll
                for (int nt = 0; nt < 4; ++nt)
                    mma_tf32(acc[mt][nt], af[mt], bf[nt]);
        }
        __syncthreads();
        if (c + 2 < 32) {
            load_stage(c & 1, (c + 2) * 16);
            CP_COMMIT();
        }
    }

#pragma unroll
    for (int mt = 0; mt < 4; ++mt) {
        int row = m0 + m0w + mt * 16 + lr;
#pragma unroll
        for (int nt = 0; nt < 4; ++nt) {
            int col = n0 + n0w + nt * 8 + lc * 2;
            *(float2*)(Out + (size_t)row * 512 + col) =
                make_float2(acc[mt][nt][0], acc[mt][nt][1]);
            *(float2*)(Out + (size_t)(row + 8) * 512 + col) =
                make_float2(acc[mt][nt][2], acc[mt][nt][3]);
        }
    }
}

// ---------------- big-branch softmax column sums -----------------------------
__global__ void __launch_bounds__(256) rel_big_kernel() {
    int side = blockIdx.x >> 2, d = blockIdx.x & 3, b = blockIdx.y;
    const float* T = (side == 0 ? g_T1 : g_T2) + (size_t)b * 512 * 512 + (4 + d) * 64;
    int t = threadIdx.x, p = t & 63, seg = t >> 6;
    float m = -1e30f, s = 0.f;
    const float* col = T + p;
    for (int h = seg * 128; h < seg * 128 + 128; ++h) {
        float v = col[(size_t)h * 512];
        if (v <= m) s += __expf(v - m);
        else { s = s * __expf(m - v) + 1.0f; m = v; }
    }
    __shared__ float sm[4][64], ss[4][64], sMp[64], sSp[64];
    __shared__ float sMg;
    sm[seg][p] = m; ss[seg][p] = s;
    __syncthreads();
    if (t < 64) {
        float M = sm[0][t];
        for (int g = 1; g < 4; g++) M = fmaxf(M, sm[g][t]);
        float S = 0.f;
        for (int g = 0; g < 4; g++) S += ss[g][t] * __expf(sm[g][t] - M);
        sMp[t] = M; sSp[t] = S;
    }
    __syncthreads();
    if (t == 0) {
        float mg = -1e30f;
        for (int q = 0; q < 64; q++) mg = fmaxf(mg, sMp[q]);
        sMg = mg;
    }
    __syncthreads();
    int base = (b * 4 + d) * 2 + side;
    if (t < 64) {
        float num = sSp[t] * __expf(sMp[t] - sMg);
        g_relnum[base * 64 + t] = num;
        sSp[t] = num;
    }
    __syncthreads();
    if (t == 0) {
        float tt = 0.f;
        for (int q = 0; q < 64; q++) tt += sSp[q];
        g_relden[base] = tt;
    }
}

// ---------------- p_t = T_proj^T @ p_w ---------------------------------------
__global__ void __launch_bounds__(256) pt_kernel(const float* __restrict__ p_xj,
                                                 const float* __restrict__ p_xi) {
    int side = blockIdx.x >> 2, d = blockIdx.x & 3, b = blockIdx.y;
    const float* T = (side == 0 ? g_T1 : g_T2) + (size_t)b * 512 * 512 + d * 64;
    const float* Wp = (side == 0 ? p_xj : p_xi) + (size_t)d * 512 * 64;
    __shared__ float At[64][68], Bt[64][68];
    int tid = threadIdx.x, tx = tid & 15, ty = tid >> 4;
    float acc[4][4];
#pragma unroll
    for (int i = 0; i < 4; i++)
#pragma unroll
        for (int j = 0; j < 4; j++) acc[i][j] = 0.f;
    for (int h0 = 0; h0 < 512; h0 += 64) {
#pragma unroll
        for (int l = 0; l < 4; ++l) {
            int pos = tid + l * 256, r = pos >> 4, c4 = pos & 15;
            *(float4*)(&At[r][c4 * 4]) = *(const float4*)(T + (size_t)(h0 + r) * 512 + c4 * 4);
            *(float4*)(&Bt[r][c4 * 4]) = *(const float4*)(Wp + (size_t)(h0 + r) * 64 + c4 * 4);
        }
        __syncthreads();
#pragma unroll 8
        for (int hh = 0; hh < 64; ++hh) {
            float4 a = *(const float4*)(&At[hh][ty * 4]);
            float4 bb = *(const float4*)(&Bt[hh][tx * 4]);
            float av[4] = {a.x, a.y, a.z, a.w}, bv[4] = {bb.x, bb.y, bb.z, bb.w};
#pragma unroll
            for (int i = 0; i < 4; i++)
#pragma unroll
                for (int j = 0; j < 4; j++) acc[i][j] += av[i] * bv[j];
        }
        __syncthreads();
    }
    float* O = g_pt + (size_t)((b * 4 + d) * 2 + side) * 4096;
#pragma unroll
    for (int i = 0; i < 4; i++)
        *(float4*)(O + (size_t)(ty * 4 + i) * 64 + tx * 4) =
            make_float4(acc[i][0], acc[i][1], acc[i][2], acc[i][3]);
}

// ---------------- per-batch epilogue -----------------------------------------
__global__ void __launch_bounds__(256) final_kernel(
    const float* __restrict__ p_rel_xj, const float* __restrict__ p_rel_xi,
    float* __restrict__ out) {
    int b = blockIdx.x, t = threadIdx.x;
    __shared__ float bufA[4096], bufB[4096];
    __shared__ float scr_m[256], scr_s[256], scr_f[64], sred[64], sVals[4];
    const int i_row = t >> 2, jbase = (t & 3) * 16;
    const float xmean = g_stats[b * 2 + 0], xstd = g_stats[b * 2 + 1];
    float outacc[16];
#pragma unroll
    for (int jj = 0; jj < 16; jj++) outacc[jj] = 0.f;

    for (int d = 0; d < 4; ++d) {
        float xbuf[16];
#pragma unroll
        for (int jj = 0; jj < 16; jj++) xbuf[jj] = 0.f;
        for (int side = 0; side < 2; ++side) {
            __syncthreads();
            const float4* P4 = (const float4*)(g_pt + (size_t)((b * 4 + d) * 2 + side) * 4096);
            const float4* R4 = (const float4*)((side == 0 ? p_rel_xj : p_rel_xi) + (size_t)d * 4096);
#pragma unroll
            for (int l = 0; l < 4; l++) {
                ((float4*)bufA)[t + l * 256] = P4[t + l * 256];
                ((float4*)bufB)[t + l * 256] = R4[t + l * 256];
            }
            __syncthreads();
            int c = t & 63, seg = t >> 6;
            float u[16];
#pragma unroll
            for (int r = 0; r < 16; r++) u[r] = 0.f;
            for (int k = 0; k < 64; ++k) {
                float bk = bufB[k * 64 + c];
#pragma unroll
                for (int r = 0; r < 16; r++)
                    u[r] += bufA[(seg * 16 + r) * 64 + k] * bk;
            }
            float m = u[0];
#pragma unroll
            for (int r = 1; r < 16; r++) m = fmaxf(m, u[r]);
            float s = 0.f;
#pragma unroll
            for (int r = 0; r < 16; r++) s += __expf(u[r] - m);
            scr_m[t] = m; scr_s[t] = s;
            __syncthreads();
            if (t < 64) {
                float M = scr_m[t];
                for (int g = 1; g < 4; g++) M = fmaxf(M, scr_m[g * 64 + t]);
                float S = 0.f;
                for (int g = 0; g < 4; g++) S += scr_s[g * 64 + t] * __expf(scr_m[g * 64 + t] - M);
                scr_m[t] = M; scr_s[t] = S;
            }
            __syncthreads();
            if (t == 0) {
                float mg = -1e30f;
                for (int q = 0; q < 64; q++) mg = fmaxf(mg, scr_m[q]);
                sVals[0] = mg;
            }
            __syncthreads();
            if (t < 64) {
                float num = scr_s[t] * __expf(scr_m[t] - sVals[0]);
                sred[t] = num; scr_s[t] = num;
            }
            __syncthreads();
            if (t == 0) {
                float tt = 0.f;
                for (int q = 0; q < 64; q++) tt += sred[q];
                sVals[1] = tt;
            }
            __syncthreads();
            int base = (b * 4 + d) * 2 + side;
            if (t < 64)
                scr_f[t] = sqrtf(g_relnum[base * 64 + t] * sVals[1] /
                                 (g_relden[base] * scr_s[t]));
            __syncthreads();
            if (side == 0) {
                float fi = scr_f[i_row];
#pragma unroll
                for (int jj = 0; jj < 16; jj++)
                    xbuf[jj] += bufA[i_row * 64 + jbase + jj] * fi;
            } else {
#pragma unroll
                for (int jj = 0; jj < 16; jj++) {
                    int j = jbase + jj;
                    xbuf[jj] += bufA[j * 64 + i_row] * scr_f[j];
                }
            }
        }
        float s1 = 0.f, s2 = 0.f;
#pragma unroll
        for (int jj = 0; jj < 16; jj++) { s1 += xbuf[jj]; s2 += xbuf[jj] * xbuf[jj]; }
        for (int o = 16; o; o >>= 1) {
            s1 += __shfl_down_sync(0xffffffffu, s1, o);
            s2 += __shfl_down_sync(0xffffffffu, s2, o);
        }
        __syncthreads();
        if ((t & 31) == 0) { scr_m[t >> 5] = s1; scr_s[t >> 5] = s2; }
        __syncthreads();
        if (t == 0) {
            float S1 = 0.f, S2 = 0.f;
            for (int wv = 0; wv < 8; wv++) { S1 += scr_m[wv]; S2 += scr_s[wv]; }
            float mean = S1 * (1.0f / 4096.0f);
            float var = (S2 - 4096.0f * mean * mean) * (1.0f / 4095.0f);
            sVals[2] = mean;
            sVals[3] = xstd / (sqrtf(var) + 1e-5f);
        }
        __syncthreads();
#pragma unroll
        for (int jj = 0; jj < 16; jj++)
            outacc[jj] += (xbuf[jj] - sVals[2]) * sVals[3] + xmean;
    }
    float* O = out + (size_t)b * 4096;
#pragma unroll
    for (int jj = 0; jj < 16; jj++)
        O[(size_t)i_row * 64 + jbase + jj] = outacc[jj];
}

// ---------------- launch ------------------------------------------------------
extern "C" void kernel_launch(void* const* d_in, const int* in_sizes, int n_in,
                              void* d_out, int out_size) {
    const float* x        = (const float*)d_in[0];
    const float* o_xj     = (const float*)d_in[1];
    const float* o_xi     = (const float*)d_in[2];
    const float* p_xj     = (const float*)d_in[3];
    const float* p_xi     = (const float*)d_in[4];
    const float* o_rel_xj = (const float*)d_in[5];
    const float* o_rel_xi = (const float*)d_in[6];
    const float* p_rel_xj = (const float*)d_in[7];
    const float* p_rel_xi = (const float*)d_in[8];
    float* out = (float*)d_out;

    pack_kernel<<<1024, 256>>>(o_xj, o_rel_xj, o_xi, o_rel_xi);
    stats_kernel<<<NB, 256>>>(x);
    gemm_tf32_kernel<0><<<dim3(4, 4, NB), 256>>>(x);
    gemm_tf32_kernel<1><<<dim3(4, 4, NB), 256>>>(x);
    rel_big_kernel<<<dim3(8, NB), 256>>>();
    pt_kernel<<<dim3(8, NB), 256>>>(p_xj, p_xi);
    final_kernel<<<NB, 256>>>(p_rel_xj, p_rel_xi, out);
}